// round 15
// baseline (speedup 1.0000x reference)
#include <cuda_runtime.h>
#include <math.h>

typedef unsigned long long ull;

#define BB 16
#define NN 500
#define TT 128
#define NP 512
#define XGC 336
#define KT 16

__device__ float g_H   [BB*64 *NP];
__device__ float g_XG5 [BB*XGC*NP];
__device__ float g_CG5 [BB*XGC*NP];
__device__ float g_XIN [BB*64 *NP];
__device__ float g_XIN2[BB*128*NP];
__device__ float g_OUT [BB*64 *NP];
__device__ float g_U   [BB*64 *NP];
__device__ float g_A2f [512*512];
__device__ float g_A2b [512*512];
__device__ float g_Wc2 [64*192];
__device__ float g_bc2 [64];

__device__ unsigned g_cnt;
__device__ volatile unsigned g_gen;

__device__ __forceinline__ ull pack2(float x, float y) {
    ull r; asm("mov.b64 %0, {%1,%2};" : "=l"(r) : "f"(x), "f"(y)); return r;
}
__device__ __forceinline__ void unpack2(ull p, float& x, float& y) {
    asm("mov.b64 {%0,%1}, %2;" : "=f"(x), "=f"(y) : "l"(p));
}
__device__ __forceinline__ void fma2(ull& d, ull a, ull b) {
    asm("fma.rn.f32x2 %0, %1, %2, %0;" : "+l"(d) : "l"(a), "l"(b));
}

__device__ __forceinline__ void gridbar() {
    __syncthreads();
    if (threadIdx.x == 0) {
        unsigned gen = g_gen;
        __threadfence();
        if (atomicAdd(&g_cnt, 1u) == gridDim.x - 1u) {
            atomicExch(&g_cnt, 0u);
            __threadfence();
            g_gen = gen + 1u;
        } else {
            while (g_gen == gen) __nanosleep(64);
        }
        __threadfence();
    }
    __syncthreads();
}

// 64x64 tile, 256 threads: tx=tid&15 (4 n), ty=tid>>4 (4 m)
__device__ __forceinline__ void mm16(const float (*sA)[68], const float (*sB)[68],
                                     ull acc[4][2], int tx, int ty) {
#pragma unroll
    for (int kk = 0; kk < KT; kk++) {
        float4 a = *(const float4*)&sA[kk][ty * 4];
        ull b0 = *(const ull*)&sB[kk][tx * 4];
        ull b1 = *(const ull*)&sB[kk][tx * 4 + 2];
        ull ap;
        ap = pack2(a.x, a.x); fma2(acc[0][0], ap, b0); fma2(acc[0][1], ap, b1);
        ap = pack2(a.y, a.y); fma2(acc[1][0], ap, b0); fma2(acc[1][1], ap, b1);
        ap = pack2(a.z, a.z); fma2(acc[2][0], ap, b0); fma2(acc[2][1], ap, b1);
        ap = pack2(a.w, a.w); fma2(acc[3][0], ap, b0); fma2(acc[3][1], ap, b1);
    }
}

// dst[b, dstOff+c, w] = sum_v src[b, srcOff+c, v] * Amat[w, v]; Amat row stride astr
// KT=32 slabs: one sync + two mm16 halves per slab.
__device__ void diff_tile(const float* __restrict__ src, float* __restrict__ dst,
                          const float* __restrict__ Amat, int astr,
                          int C, int srcOff, int dstOff, int srcBS, int dstBS,
                          int m0, int n0,
                          float (*sAb)[68], float (*sBb)[68])
{
    const int tid = threadIdx.x;
    const int M = C * BB;
    const int r = tid & 63, ks = tid >> 6, koff = ks * 8;

    const float* srow = 0;
    { int gm = m0 + r;
      if (gm < M) { int b = gm / C, c = gm - b * C;
          srow = src + (size_t)b * srcBS + (size_t)(srcOff + c) * NP; } }
    const float* arow = 0;
    { int gn = n0 + r; if (gn < NN) arow = Amat + (size_t)gn * astr; }

    const int tx = tid & 15, ty = tid >> 4;
    ull acc[4][2] = {};
    const float4 Z = make_float4(0.f, 0.f, 0.f, 0.f);
    float4 va0 = srow ? *(const float4*)(srow + koff) : Z;
    float4 va1 = srow ? *(const float4*)(srow + koff + 4) : Z;
    float4 vb0 = (arow && koff     < NN) ? *(const float4*)(arow + koff) : Z;
    float4 vb1 = (arow && koff + 4 < NN) ? *(const float4*)(arow + koff + 4) : Z;

    int buf = 0;
    for (int k0 = 0; k0 < NP; k0 += 32) {
        float (*sA)[68] = sAb + buf * 32;
        float (*sB)[68] = sBb + buf * 32;
        sA[koff+0][r] = va0.x; sA[koff+1][r] = va0.y;
        sA[koff+2][r] = va0.z; sA[koff+3][r] = va0.w;
        sA[koff+4][r] = va1.x; sA[koff+5][r] = va1.y;
        sA[koff+6][r] = va1.z; sA[koff+7][r] = va1.w;
        sB[koff+0][r] = vb0.x; sB[koff+1][r] = vb0.y;
        sB[koff+2][r] = vb0.z; sB[koff+3][r] = vb0.w;
        sB[koff+4][r] = vb1.x; sB[koff+5][r] = vb1.y;
        sB[koff+6][r] = vb1.z; sB[koff+7][r] = vb1.w;
        __syncthreads();
        int kn = k0 + 32;
        if (kn < NP) {
            int kb = kn + koff;
            va0 = srow ? *(const float4*)(srow + kb) : Z;
            va1 = srow ? *(const float4*)(srow + kb + 4) : Z;
            vb0 = (arow && kb     < NN) ? *(const float4*)(arow + kb) : Z;
            vb1 = (arow && kb + 4 < NN) ? *(const float4*)(arow + kb + 4) : Z;
        }
        mm16(sA, sB, acc, tx, ty);
        mm16(sA + 16, sB + 16, acc, tx, ty);
        buf ^= 1;
    }

#pragma unroll
    for (int i = 0; i < 4; i++) {
        int gm = m0 + ty * 4 + i;
        if (gm >= M) continue;
        int b = gm / C, c = gm - b * C;
        float* drow = dst + (size_t)b * dstBS + (size_t)(dstOff + c) * NP;
#pragma unroll
        for (int j = 0; j < 2; j++) {
            int gn = n0 + tx * 4 + 2 * j;
            if (gn < NN) {
                float v0, v1; unpack2(acc[i][j], v0, v1);
                *(float2*)(drow + gn) = make_float2(v0, v1);
            }
        }
    }
}

// A2[w,u] = sum_v A[w,v] * A[v,u]; dst row stride 512  (prologue only, KT=16)
__device__ void a2_tile(const float* __restrict__ A, float* __restrict__ dst,
                        int m0, int n0, float (*sAb)[68], float (*sBb)[68])
{
    const int tid = threadIdx.x;
    const int r = tid >> 2, kr = tid & 3, koff = kr * 4;
    const int kx = tid >> 4, nc = (tid & 15) * 4;
    const int tx = tid & 15, ty = tid >> 4;

    const float* srow = (m0 + r < NN) ? A + (size_t)(m0 + r) * NN : 0;
    const bool ncok = (n0 + nc < NN);

    ull acc[4][2] = {};
    const float4 Z = make_float4(0.f, 0.f, 0.f, 0.f);
    float4 va = srow ? *(const float4*)(srow + koff) : Z;
    float4 vx = (kx < NN && ncok) ? *(const float4*)(A + (size_t)kx * NN + n0 + nc) : Z;

    int kt = 0;
    for (int k0 = 0; k0 < NN; k0 += KT, kt++) {
        float (*sA)[68] = sAb + (kt & 1) * KT;
        float (*sB)[68] = sBb + (kt & 1) * KT;
        sA[kr*4+0][r] = va.x; sA[kr*4+1][r] = va.y;
        sA[kr*4+2][r] = va.z; sA[kr*4+3][r] = va.w;
        *(float4*)&sB[kx][nc] = vx;
        __syncthreads();
        int kn = k0 + KT;
        if (kn < NN) {
            va = (srow && kn + koff < NN) ? *(const float4*)(srow + kn + koff) : Z;
            int kg = kn + kx;
            vx = (kg < NN && ncok) ? *(const float4*)(A + (size_t)kg * NN + n0 + nc) : Z;
        }
        mm16(sA, sB, acc, tx, ty);
    }

#pragma unroll
    for (int i = 0; i < 4; i++) {
        int gm = m0 + ty * 4 + i;
        if (gm >= NN) continue;
        float* drow = dst + (size_t)gm * 512;
#pragma unroll
        for (int j = 0; j < 2; j++) {
            int gn = n0 + tx * 4 + 2 * j;
            if (gn < NN) {
                float v0, v1; unpack2(acc[i][j], v0, v1);
                *(float2*)(drow + gn) = make_float2(v0, v1);
            }
        }
    }
}

// out[b,o,n] = act(sum_k W[o,k]*X[b,k,n] + bias[o]); X = concat(S1,S2)
// mode 0:->dst | 1: prelu->g_OUT+reps | 2: sigmoid->g_U
// 3: sigmoid*h->CG5[2+o] | 4: tanh, h=u*h+(1-u)*c
__device__ void conv_tile(const float* __restrict__ S1, int C1, int s1BS,
                          const float* __restrict__ S2, int s2BS,
                          const float* __restrict__ W, const float* __restrict__ bias,
                          int K, int b, int n0, int mode,
                          float* __restrict__ dst, float* __restrict__ reps,
                          int t, float pav,
                          float (*sAb)[68], float (*sBb)[68])
{
    const int tid = threadIdx.x;
    const int o_l = tid & 63, kq = (tid >> 6) * 4;
    const int kx = tid >> 4, nc = (tid & 15) * 4;
    const int tx = tid & 15, ty = tid >> 4;

    ull acc[4][2] = {};
    float w0, w1, w2, w3;
    float4 vx;
    {
        w0 = (kq + 0 < K) ? W[(size_t)o_l * K + kq + 0] : 0.f;
        w1 = (kq + 1 < K) ? W[(size_t)o_l * K + kq + 1] : 0.f;
        w2 = (kq + 2 < K) ? W[(size_t)o_l * K + kq + 2] : 0.f;
        w3 = (kq + 3 < K) ? W[(size_t)o_l * K + kq + 3] : 0.f;
        const float* row = (kx < C1) ? S1 + (size_t)b * s1BS + (size_t)kx * NP
                                     : S2 + (size_t)b * s2BS + (size_t)(kx - C1) * NP;
        vx = *(const float4*)(row + n0 + nc);
    }

    int kt = 0;
    for (int k0 = 0; k0 < K; k0 += KT, kt++) {
        float (*sA)[68] = sAb + (kt & 1) * KT;
        float (*sB)[68] = sBb + (kt & 1) * KT;
        sA[kq+0][o_l] = w0; sA[kq+1][o_l] = w1;
        sA[kq+2][o_l] = w2; sA[kq+3][o_l] = w3;
        *(float4*)&sB[kx][nc] = vx;
        __syncthreads();
        int kn = k0 + KT;
        if (kn < K) {
            int kg0 = kn + kq;
            w0 = (kg0 + 0 < K) ? W[(size_t)o_l * K + kg0 + 0] : 0.f;
            w1 = (kg0 + 1 < K) ? W[(size_t)o_l * K + kg0 + 1] : 0.f;
            w2 = (kg0 + 2 < K) ? W[(size_t)o_l * K + kg0 + 2] : 0.f;
            w3 = (kg0 + 3 < K) ? W[(size_t)o_l * K + kg0 + 3] : 0.f;
            int kg = kn + kx;
            const float* row = (kg < C1) ? S1 + (size_t)b * s1BS + (size_t)kg * NP
                                         : S2 + (size_t)b * s2BS + (size_t)(kg - C1) * NP;
            vx = *(const float4*)(row + n0 + nc);
        }
        mm16(sA, sB, acc, tx, ty);
    }

#pragma unroll
    for (int i = 0; i < 4; i++) {
        int o = ty * 4 + i;
        float bs = bias[o];
        size_t rowIdx = ((size_t)b * 64 + o) * NP;
#pragma unroll
        for (int j = 0; j < 2; j++) {
            int gn = n0 + tx * 4 + 2 * j;
            if (gn >= NN) continue;
            float v0, v1; unpack2(acc[i][j], v0, v1);
            v0 += bs; v1 += bs;
            if (mode == 0) {
                *(float2*)(dst + rowIdx + gn) = make_float2(v0, v1);
            } else if (mode == 1) {
                float o0 = v0 >= 0.f ? v0 : pav * v0;
                float o1 = v1 >= 0.f ? v1 : pav * v1;
                *(float2*)(g_OUT + rowIdx + gn) = make_float2(o0, o1);
                size_t rb = (((size_t)b * 128 + o) * NN + gn) * TT + t;
                reps[rb] = o0; reps[rb + TT] = o1;
            } else if (mode == 2) {
                *(float2*)(g_U + rowIdx + gn) =
                    make_float2(1.f / (1.f + expf(-v0)), 1.f / (1.f + expf(-v1)));
            } else if (mode == 3) {
                float2 h2 = *(const float2*)(g_H + rowIdx + gn);
                *(float2*)(g_CG5 + ((size_t)b * XGC + 2 + o) * NP + gn) =
                    make_float2(h2.x / (1.f + expf(-v0)), h2.y / (1.f + expf(-v1)));
            } else {
                float c0 = tanhf(v0), c1 = tanhf(v1);
                float2 u2 = *(const float2*)(g_U + rowIdx + gn);
                float2 h2 = *(const float2*)(g_H + rowIdx + gn);
                *(float2*)(g_H + rowIdx + gn) =
                    make_float2(u2.x * h2.x + (1.f - u2.x) * c0,
                                u2.y * h2.y + (1.f - u2.y) * c1);
            }
        }
    }
}

__global__ void __launch_bounds__(256, 2) kmain(
    const float* __restrict__ x, const float* __restrict__ af,
    const float* __restrict__ ab, const int* __restrict__ mask,
    const float* __restrict__ Wr,  const float* __restrict__ br,
    const float* __restrict__ Wu,  const float* __restrict__ bu,
    const float* __restrict__ Wc,  const float* __restrict__ bc,
    const float* __restrict__ Wfs, const float* __restrict__ bfs,
    const float* __restrict__ Wli, const float* __restrict__ bli,
    const float* __restrict__ Wgc, const float* __restrict__ bgc,
    const float* __restrict__ Wlo, const float* __restrict__ blo,
    const float* __restrict__ Wro, const float* __restrict__ bro,
    const float* __restrict__ pa,
    float* __restrict__ imp, float* __restrict__ pred, float* __restrict__ reps)
{
    __shared__ __align__(16) float sA[64][68];
    __shared__ __align__(16) float sB[64][68];

    const int tid  = threadIdx.x;
    const int nb   = gridDim.x;
    const int bid  = blockIdx.x;
    const int gtid = bid * 256 + tid;
    const int gstr = nb * 256;
    const float pav = *pa;

    // ---- prologue: zero H; fold W_gc into W_lo; A^2 for both supports ----
    for (int i = gtid; i < BB * 64 * NP; i += gstr) g_H[i] = 0.f;
    for (int i = gtid; i < 64 * 192; i += gstr) {
        int o = i / 192, k = i - o * 192;
        float s;
        if (k < 128) {
            s = 0.f;
            for (int j = 0; j < 64; j++) s += Wlo[o * 128 + j] * Wgc[j * 128 + k];
        } else s = Wlo[o * 128 + 64 + (k - 128)];
        g_Wc2[i] = s;
    }
    for (int i = gtid; i < 64; i += gstr) {
        float s = blo[i];
        for (int j = 0; j < 64; j++) s += Wlo[i * 128 + j] * bgc[j];
        g_bc2[i] = s;
    }
    for (int tile = bid; tile < 128; tile += nb) {
        int z = tile >> 6, rem = tile & 63;
        a2_tile(z ? ab : af, z ? g_A2b : g_A2f,
                (rem >> 3) * 64, (rem & 7) * 64, sA, sB);
    }
    gridbar();

    for (int t = 0; t < TT; t++) {
        // stage A: pred, x1, mf; pack XG5 h; CG5 mf; reps h-half
        for (int i = gtid; i < BB * NN; i += gstr) {
            int b = i / NN, n = i - b * NN;
            const float* h = g_H + (size_t)b * 64 * NP + n;
            float* xg = g_XG5 + (size_t)b * XGC * NP + n;
            float* rb = reps + (((size_t)b * 128 + 64) * NN + n) * TT + t;
            float s = bfs[0];
#pragma unroll 8
            for (int c = 0; c < 64; c++) {
                float hv = h[(size_t)c * NP];
                s += Wfs[c] * hv;
                xg[(size_t)(2 + c) * NP] = hv;
                rb[(size_t)c * NN * TT] = hv;
            }
            size_t xi = ((size_t)b * NN + n) * TT + t;
            pred[xi] = s;
            int mk = mask[xi];
            xg[0]  = mk ? x[xi] : s;
            xg[NP] = (float)mk;
            g_CG5[(size_t)b * XGC * NP + NP + n] = (float)mk;
        }
        gridbar();

        // conv li (K=66): XG5[0..65] -> XIN
        for (int tile = bid; tile < 128; tile += nb)
            conv_tile(g_XG5, 1000, XGC * NP, g_XG5, 0, Wli, bli, 66,
                      tile >> 3, (tile & 7) * 64, 0, g_XIN, reps, t, pav, sA, sB);
        gridbar();

        // diffusion XIN -> XIN2 (order-1, both supports)
        for (int tile = bid; tile < 256; tile += nb) {
            int z = tile >> 7, rem = tile & 127;
            diff_tile(g_XIN, g_XIN2, z ? ab : af, NN, 64, 0, z * 64,
                      64 * NP, 128 * NP, (rem >> 3) * 64, (rem & 7) * 64, sA, sB);
        }
        gridbar();

        // combined gc∘lo conv (K=192) -> OUT (prelu) + reps
        for (int tile = bid; tile < 128; tile += nb)
            conv_tile(g_XIN2, 128, 128 * NP, g_H, 64 * NP, g_Wc2, g_bc2, 192,
                      tile >> 3, (tile & 7) * 64, 1, g_OUT, reps, t, pav, sA, sB);
        gridbar();

        // stage B: imp, x2 -> XG5[0], CG5[0]
        for (int i = gtid; i < BB * NN; i += gstr) {
            int b = i / NN, n = i - b * NN;
            const float* o = g_OUT + (size_t)b * 64 * NP + n;
            const float* h = g_H   + (size_t)b * 64 * NP + n;
            float s = bro[0];
#pragma unroll 8
            for (int c = 0; c < 64; c++)
                s += Wro[c] * o[(size_t)c * NP] + Wro[64 + c] * h[(size_t)c * NP];
            size_t xi = ((size_t)b * NN + n) * TT + t;
            imp[xi] = s;
            int mk = mask[xi];
            float* xg0 = g_XG5 + (size_t)b * XGC * NP + n;
            float x2 = mk ? *xg0 : s;
            *xg0 = x2;
            g_CG5[(size_t)b * XGC * NP + n] = x2;
        }
        gridbar();

        // XG diffusion: both hops in ONE stage via A and A^2 (independent)
        for (int tile = bid; tile < 544; tile += nb) {
            int hop = tile / 272, rem = tile - hop * 272;
            int z = rem / 136, r2 = rem - z * 136;
            const float* Am = hop ? (z ? g_A2b : g_A2f) : (z ? ab : af);
            diff_tile(g_XG5, g_XG5, Am, hop ? 512 : NN, 66, 0,
                      66 + z * 132 + hop * 66,
                      XGC * NP, XGC * NP, (r2 >> 3) * 64, (r2 & 7) * 64, sA, sB);
        }
        gridbar();

        // convs r (-> r*h into CG5[2..65]) and u (-> U)
        for (int tile = bid; tile < 256; tile += nb) {
            int tl = tile & 127;
            if (tile < 128)
                conv_tile(g_XG5, 1000, XGC * NP, g_XG5, 0, Wr, br, 330,
                          tl >> 3, (tl & 7) * 64, 3, g_U, reps, t, pav, sA, sB);
            else
                conv_tile(g_XG5, 1000, XGC * NP, g_XG5, 0, Wu, bu, 330,
                          tl >> 3, (tl & 7) * 64, 2, g_U, reps, t, pav, sA, sB);
        }
        gridbar();

        // CG diffusion: both hops in ONE stage
        for (int tile = bid; tile < 544; tile += nb) {
            int hop = tile / 272, rem = tile - hop * 272;
            int z = rem / 136, r2 = rem - z * 136;
            const float* Am = hop ? (z ? g_A2b : g_A2f) : (z ? ab : af);
            diff_tile(g_CG5, g_CG5, Am, hop ? 512 : NN, 66, 0,
                      66 + z * 132 + hop * 66,
                      XGC * NP, XGC * NP, (r2 >> 3) * 64, (r2 & 7) * 64, sA, sB);
        }
        gridbar();

        // conv c (K=330): tanh + h = u*h + (1-u)*c
        for (int tile = bid; tile < 128; tile += nb)
            conv_tile(g_CG5, 1000, XGC * NP, g_CG5, 0, Wc, bc, 330,
                      tile >> 3, (tile & 7) * 64, 4, g_U, reps, t, pav, sA, sB);
        gridbar();
    }
}

extern "C" void kernel_launch(void* const* d_in, const int* in_sizes, int n_in,
                              void* d_out, int out_size)
{
    const float* x    = (const float*)d_in[0];
    const float* af   = (const float*)d_in[1];
    const float* ab   = (const float*)d_in[2];
    const int*   mask = (const int*)  d_in[3];
    const float* Wr   = (const float*)d_in[4];
    const float* br   = (const float*)d_in[5];
    const float* Wu   = (const float*)d_in[6];
    const float* bu   = (const float*)d_in[7];
    const float* Wc   = (const float*)d_in[8];
    const float* bc   = (const float*)d_in[9];
    const float* Wfs  = (const float*)d_in[10];
    const float* bfs  = (const float*)d_in[11];
    const float* Wli  = (const float*)d_in[12];
    const float* bli  = (const float*)d_in[13];
    const float* Wgc  = (const float*)d_in[14];
    const float* bgc  = (const float*)d_in[15];
    const float* Wlo  = (const float*)d_in[16];
    const float* blo  = (const float*)d_in[17];
    const float* Wro  = (const float*)d_in[18];
    const float* bro  = (const float*)d_in[19];
    const float* pa   = (const float*)d_in[20];

    float* out_imp  = (float*)d_out;
    float* out_pred = out_imp + (size_t)BB * NN * TT;
    float* out_reps = out_imp + (size_t)2 * BB * NN * TT;

    int dev = 0; cudaGetDevice(&dev);
    int sm = 0;
    cudaDeviceGetAttribute(&sm, cudaDevAttrMultiProcessorCount, dev);
    if (sm <= 0) sm = 148;
    int per = 0;
    cudaOccupancyMaxActiveBlocksPerMultiprocessor(&per, kmain, 256, 0);
    if (per < 1) per = 1;
    if (per > 2) per = 2;
    int nb = sm * per;

    kmain<<<nb, 256>>>(x, af, ab, mask, Wr, br, Wu, bu, Wc, bc,
                       Wfs, bfs, Wli, bli, Wgc, bgc, Wlo, blo, Wro, bro, pa,
                       out_imp, out_pred, out_reps);
}

// round 16
// speedup vs baseline: 1.1861x; 1.1861x over previous
#include <cuda_runtime.h>
#include <math.h>

typedef unsigned long long ull;

#define BB 16
#define NN 500
#define TT 128
#define NP 512
#define XGC 336
#define KT 16

__device__ float g_H   [BB*64 *NP];
__device__ float g_XG5 [BB*XGC*NP];
__device__ float g_CG5 [BB*XGC*NP];
__device__ float g_XIN2[BB*128*NP];
__device__ float g_OUT [BB*64 *NP];
__device__ float g_R   [BB*64 *NP];
__device__ float g_U   [BB*64 *NP];
__device__ float g_A2f [512*512];
__device__ float g_A2b [512*512];
__device__ float g_Wc2 [64*192];
__device__ float g_bc2 [64];
__device__ float g_Wr0 [64*330];
__device__ float g_Wu0 [64*330];
__device__ float g_Wr4 [64*4];
__device__ float g_Wu4 [64*4];

__device__ unsigned g_cnt;
__device__ volatile unsigned g_gen;

__device__ __forceinline__ ull pack2(float x, float y) {
    ull r; asm("mov.b64 %0, {%1,%2};" : "=l"(r) : "f"(x), "f"(y)); return r;
}
__device__ __forceinline__ void unpack2(ull p, float& x, float& y) {
    asm("mov.b64 {%0,%1}, %2;" : "=f"(x), "=f"(y) : "l"(p));
}
__device__ __forceinline__ void fma2(ull& d, ull a, ull b) {
    asm("fma.rn.f32x2 %0, %1, %2, %0;" : "+l"(d) : "l"(a), "l"(b));
}

__device__ __forceinline__ void gridbar() {
    __syncthreads();
    if (threadIdx.x == 0) {
        unsigned gen = g_gen;
        __threadfence();
        if (atomicAdd(&g_cnt, 1u) == gridDim.x - 1u) {
            atomicExch(&g_cnt, 0u);
            __threadfence();
            g_gen = gen + 1u;
        } else {
            while (g_gen == gen) __nanosleep(64);
        }
        __threadfence();
    }
    __syncthreads();
}

// 64x64 tile, 256 threads: tx=tid&15 (4 n), ty=tid>>4 (4 m)
__device__ __forceinline__ void mm16(const float (*sA)[68], const float (*sB)[68],
                                     ull acc[4][2], int tx, int ty) {
#pragma unroll
    for (int kk = 0; kk < KT; kk++) {
        float4 a = *(const float4*)&sA[kk][ty * 4];
        ull b0 = *(const ull*)&sB[kk][tx * 4];
        ull b1 = *(const ull*)&sB[kk][tx * 4 + 2];
        ull ap;
        ap = pack2(a.x, a.x); fma2(acc[0][0], ap, b0); fma2(acc[0][1], ap, b1);
        ap = pack2(a.y, a.y); fma2(acc[1][0], ap, b0); fma2(acc[1][1], ap, b1);
        ap = pack2(a.z, a.z); fma2(acc[2][0], ap, b0); fma2(acc[2][1], ap, b1);
        ap = pack2(a.w, a.w); fma2(acc[3][0], ap, b0); fma2(acc[3][1], ap, b1);
    }
}

// dst[b, dstOff+c, w] = sum_v src[b, srcOff+c, v] * Amat[w, v]; Amat row stride astr
__device__ void diff_tile(const float* __restrict__ src, float* __restrict__ dst,
                          const float* __restrict__ Amat, int astr,
                          int C, int srcOff, int dstOff, int srcBS, int dstBS,
                          int m0, int n0,
                          float (*sAb)[68], float (*sBb)[68])
{
    const int tid = threadIdx.x;
    const int M = C * BB;
    const int r = tid >> 2, kr = tid & 3, koff = kr * 4;

    const float* srow = 0;
    { int gm = m0 + r;
      if (gm < M) { int b = gm / C, c = gm - b * C;
          srow = src + (size_t)b * srcBS + (size_t)(srcOff + c) * NP; } }
    const float* arow = 0;
    { int gn = n0 + r; if (gn < NN) arow = Amat + (size_t)gn * astr; }

    const int tx = tid & 15, ty = tid >> 4;
    ull acc[4][2] = {};
    const float4 Z = make_float4(0.f, 0.f, 0.f, 0.f);
    float4 va = srow ? *(const float4*)(srow + koff) : Z;
    float4 vb = (arow && koff < NN) ? *(const float4*)(arow + koff) : Z;

    int kt = 0;
    for (int k0 = 0; k0 < NN; k0 += KT, kt++) {
        float (*sA)[68] = sAb + (kt & 1) * KT;
        float (*sB)[68] = sBb + (kt & 1) * KT;
        sA[kr*4+0][r] = va.x; sA[kr*4+1][r] = va.y;
        sA[kr*4+2][r] = va.z; sA[kr*4+3][r] = va.w;
        sB[kr*4+0][r] = vb.x; sB[kr*4+1][r] = vb.y;
        sB[kr*4+2][r] = vb.z; sB[kr*4+3][r] = vb.w;
        __syncthreads();
        int kn = k0 + KT;
        if (kn < NN) {
            va = srow ? *(const float4*)(srow + kn + koff) : Z;
            vb = (arow && kn + koff < NN) ? *(const float4*)(arow + kn + koff) : Z;
        }
        mm16(sA, sB, acc, tx, ty);
    }

#pragma unroll
    for (int i = 0; i < 4; i++) {
        int gm = m0 + ty * 4 + i;
        if (gm >= M) continue;
        int b = gm / C, c = gm - b * C;
        float* drow = dst + (size_t)b * dstBS + (size_t)(dstOff + c) * NP;
#pragma unroll
        for (int j = 0; j < 2; j++) {
            int gn = n0 + tx * 4 + 2 * j;
            if (gn < NN) {
                float v0, v1; unpack2(acc[i][j], v0, v1);
                *(float2*)(drow + gn) = make_float2(v0, v1);
            }
        }
    }
}

// A2[w,u] = sum_v A[w,v] * A[v,u]; dst row stride 512
__device__ void a2_tile(const float* __restrict__ A, float* __restrict__ dst,
                        int m0, int n0, float (*sAb)[68], float (*sBb)[68])
{
    const int tid = threadIdx.x;
    const int r = tid >> 2, kr = tid & 3, koff = kr * 4;
    const int kx = tid >> 4, nc = (tid & 15) * 4;
    const int tx = tid & 15, ty = tid >> 4;

    const float* srow = (m0 + r < NN) ? A + (size_t)(m0 + r) * NN : 0;
    const bool ncok = (n0 + nc < NN);

    ull acc[4][2] = {};
    const float4 Z = make_float4(0.f, 0.f, 0.f, 0.f);
    float4 va = srow ? *(const float4*)(srow + koff) : Z;
    float4 vx = (kx < NN && ncok) ? *(const float4*)(A + (size_t)kx * NN + n0 + nc) : Z;

    int kt = 0;
    for (int k0 = 0; k0 < NN; k0 += KT, kt++) {
        float (*sA)[68] = sAb + (kt & 1) * KT;
        float (*sB)[68] = sBb + (kt & 1) * KT;
        sA[kr*4+0][r] = va.x; sA[kr*4+1][r] = va.y;
        sA[kr*4+2][r] = va.z; sA[kr*4+3][r] = va.w;
        *(float4*)&sB[kx][nc] = vx;
        __syncthreads();
        int kn = k0 + KT;
        if (kn < NN) {
            va = (srow && kn + koff < NN) ? *(const float4*)(srow + kn + koff) : Z;
            int kg = kn + kx;
            vx = (kg < NN && ncok) ? *(const float4*)(A + (size_t)kg * NN + n0 + nc) : Z;
        }
        mm16(sA, sB, acc, tx, ty);
    }

#pragma unroll
    for (int i = 0; i < 4; i++) {
        int gm = m0 + ty * 4 + i;
        if (gm >= NN) continue;
        float* drow = dst + (size_t)gm * 512;
#pragma unroll
        for (int j = 0; j < 2; j++) {
            int gn = n0 + tx * 4 + 2 * j;
            if (gn < NN) {
                float v0, v1; unpack2(acc[i][j], v0, v1);
                *(float2*)(drow + gn) = make_float2(v0, v1);
            }
        }
    }
}

// out[b,o,n] = act(sum_k W[o,k]*X[b,k,n] + bias[o]); X = concat(S1,S2)
// mode 0: -> dst (batch stride dstBS) | 1: prelu->g_OUT+reps
// 4: tanh, h=u*h+(1-u)*c
__device__ void conv_tile(const float* __restrict__ S1, int C1, size_t s1BS,
                          const float* __restrict__ S2, size_t s2BS,
                          const float* __restrict__ W, const float* __restrict__ bias,
                          int K, int b, int n0, int mode,
                          float* __restrict__ dst, size_t dstBS,
                          float* __restrict__ reps,
                          int t, float pav,
                          float (*sAb)[68], float (*sBb)[68])
{
    const int tid = threadIdx.x;
    const int o_l = tid & 63, kq = (tid >> 6) * 4;
    const int kx = tid >> 4, nc = (tid & 15) * 4;
    const int tx = tid & 15, ty = tid >> 4;

    ull acc[4][2] = {};
    float w0, w1, w2, w3;
    float4 vx;
    {
        w0 = (kq + 0 < K) ? W[(size_t)o_l * K + kq + 0] : 0.f;
        w1 = (kq + 1 < K) ? W[(size_t)o_l * K + kq + 1] : 0.f;
        w2 = (kq + 2 < K) ? W[(size_t)o_l * K + kq + 2] : 0.f;
        w3 = (kq + 3 < K) ? W[(size_t)o_l * K + kq + 3] : 0.f;
        const float* row = (kx < C1) ? S1 + (size_t)b * s1BS + (size_t)kx * NP
                                     : S2 + (size_t)b * s2BS + (size_t)(kx - C1) * NP;
        vx = *(const float4*)(row + n0 + nc);
    }

    int kt = 0;
    for (int k0 = 0; k0 < K; k0 += KT, kt++) {
        float (*sA)[68] = sAb + (kt & 1) * KT;
        float (*sB)[68] = sBb + (kt & 1) * KT;
        sA[kq+0][o_l] = w0; sA[kq+1][o_l] = w1;
        sA[kq+2][o_l] = w2; sA[kq+3][o_l] = w3;
        *(float4*)&sB[kx][nc] = vx;
        __syncthreads();
        int kn = k0 + KT;
        if (kn < K) {
            int kg0 = kn + kq;
            w0 = (kg0 + 0 < K) ? W[(size_t)o_l * K + kg0 + 0] : 0.f;
            w1 = (kg0 + 1 < K) ? W[(size_t)o_l * K + kg0 + 1] : 0.f;
            w2 = (kg0 + 2 < K) ? W[(size_t)o_l * K + kg0 + 2] : 0.f;
            w3 = (kg0 + 3 < K) ? W[(size_t)o_l * K + kg0 + 3] : 0.f;
            int kg = kn + kx;
            const float* row = (kg < C1) ? S1 + (size_t)b * s1BS + (size_t)kg * NP
                                         : S2 + (size_t)b * s2BS + (size_t)(kg - C1) * NP;
            vx = *(const float4*)(row + n0 + nc);
        }
        mm16(sA, sB, acc, tx, ty);
    }

#pragma unroll
    for (int i = 0; i < 4; i++) {
        int o = ty * 4 + i;
        float bs = bias[o];
        size_t rowIdx = ((size_t)b * 64 + o) * NP;
#pragma unroll
        for (int j = 0; j < 2; j++) {
            int gn = n0 + tx * 4 + 2 * j;
            if (gn >= NN) continue;
            float v0, v1; unpack2(acc[i][j], v0, v1);
            v0 += bs; v1 += bs;
            if (mode == 0) {
                *(float2*)(dst + (size_t)b * dstBS + (size_t)o * NP + gn) =
                    make_float2(v0, v1);
            } else if (mode == 1) {
                float o0 = v0 >= 0.f ? v0 : pav * v0;
                float o1 = v1 >= 0.f ? v1 : pav * v1;
                *(float2*)(g_OUT + rowIdx + gn) = make_float2(o0, o1);
                size_t rb = (((size_t)b * 128 + o) * NN + gn) * TT + t;
                reps[rb] = o0; reps[rb + TT] = o1;
            } else {
                float c0 = tanhf(v0), c1 = tanhf(v1);
                float2 u2 = *(const float2*)(g_U + rowIdx + gn);
                float2 h2 = *(const float2*)(g_H + rowIdx + gn);
                *(float2*)(g_H + rowIdx + gn) =
                    make_float2(u2.x * h2.x + (1.f - u2.x) * c0,
                                u2.y * h2.y + (1.f - u2.y) * c1);
            }
        }
    }
}

__global__ void __launch_bounds__(256, 2) kmain(
    const float* __restrict__ x, const float* __restrict__ af,
    const float* __restrict__ ab, const int* __restrict__ mask,
    const float* __restrict__ Wr,  const float* __restrict__ br,
    const float* __restrict__ Wu,  const float* __restrict__ bu,
    const float* __restrict__ Wc,  const float* __restrict__ bc,
    const float* __restrict__ Wfs, const float* __restrict__ bfs,
    const float* __restrict__ Wli, const float* __restrict__ bli,
    const float* __restrict__ Wgc, const float* __restrict__ bgc,
    const float* __restrict__ Wlo, const float* __restrict__ blo,
    const float* __restrict__ Wro, const float* __restrict__ bro,
    const float* __restrict__ pa,
    float* __restrict__ imp, float* __restrict__ pred, float* __restrict__ reps)
{
    __shared__ __align__(16) float sA[2 * KT][68];
    __shared__ __align__(16) float sB[2 * KT][68];

    const int tid  = threadIdx.x;
    const int nb   = gridDim.x;
    const int bid  = blockIdx.x;
    const int gtid = bid * 256 + tid;
    const int gstr = nb * 256;
    const float pav = *pa;

    // ---- prologue ----
    for (int i = gtid; i < BB * 64 * NP; i += gstr) g_H[i] = 0.f;
    for (int i = gtid; i < 64 * 192; i += gstr) {
        int o = i / 192, k = i - o * 192;
        float s;
        if (k < 128) {
            s = 0.f;
            for (int j = 0; j < 64; j++) s += Wlo[o * 128 + j] * Wgc[j * 128 + k];
        } else s = Wlo[o * 128 + 64 + (k - 128)];
        g_Wc2[i] = s;
    }
    for (int i = gtid; i < 64; i += gstr) {
        float s = blo[i];
        for (int j = 0; j < 64; j++) s += Wlo[i * 128 + j] * bgc[j];
        g_bc2[i] = s;
    }
    // zero-x-column gate weights + rank-4 columns (slots 66,132,198,264)
    for (int i = gtid; i < 64 * 330; i += gstr) {
        int k = i % 330;
        bool xs = (k == 66 || k == 132 || k == 198 || k == 264);
        g_Wr0[i] = xs ? 0.f : Wr[i];
        g_Wu0[i] = xs ? 0.f : Wu[i];
    }
    for (int i = gtid; i < 64 * 4; i += gstr) {
        int o = i >> 2, j = i & 3;
        g_Wr4[i] = Wr[o * 330 + 66 * (j + 1)];
        g_Wu4[i] = Wu[o * 330 + 66 * (j + 1)];
    }
    for (int tile = bid; tile < 128; tile += nb) {
        int z = tile >> 6, rem = tile & 63;
        a2_tile(z ? ab : af, z ? g_A2b : g_A2f,
                (rem >> 3) * 64, (rem & 7) * 64, sA, sB);
    }
    gridbar();

    for (int t = 0; t < TT; t++) {
        // ewA: pred, x1, mf; pack XG5 h; CG5 mf; reps h-half
        for (int i = gtid; i < BB * NN; i += gstr) {
            int b = i / NN, n = i - b * NN;
            const float* h = g_H + (size_t)b * 64 * NP + n;
            float* xg = g_XG5 + (size_t)b * XGC * NP + n;
            float* rb = reps + (((size_t)b * 128 + 64) * NN + n) * TT + t;
            float s = bfs[0];
#pragma unroll 8
            for (int c = 0; c < 64; c++) {
                float hv = h[(size_t)c * NP];
                s += Wfs[c] * hv;
                xg[(size_t)(2 + c) * NP] = hv;
                rb[(size_t)c * NN * TT] = hv;
            }
            size_t xi = ((size_t)b * NN + n) * TT + t;
            pred[xi] = s;
            int mk = mask[xi];
            xg[0]  = mk ? x[xi] : s;
            xg[NP] = (float)mk;
            g_CG5[(size_t)b * XGC * NP + NP + n] = (float)mk;
        }
        gridbar();

        // DIFF544: XG hops of [x1, mf, h] via A and A^2, both supports
        for (int tile = bid; tile < 544; tile += nb) {
            int hop = tile / 272, rem = tile - hop * 272;
            int z = rem / 136, r2 = rem - z * 136;
            const float* Am = hop ? (z ? g_A2b : g_A2f) : (z ? ab : af);
            diff_tile(g_XG5, g_XG5, Am, hop ? 512 : NN, 66, 0,
                      66 + z * 132 + hop * 66,
                      XGC * NP, XGC * NP, (r2 >> 3) * 64, (r2 & 7) * 64, sA, sB);
        }
        gridbar();

        // LI2: XIN2[z*64..] = W_li . hop1_z block (K=66) — replaces li+diff1
        for (int tile = bid; tile < 256; tile += nb) {
            int z = tile >> 7, tl = tile & 127;
            conv_tile(g_XG5 + (size_t)(66 + z * 132) * NP, 1000, (size_t)XGC * NP,
                      g_XG5, 0, Wli, bli, 66,
                      tl >> 3, (tl & 7) * 64, 0,
                      g_XIN2 + (size_t)z * 64 * NP, (size_t)128 * NP,
                      reps, t, pav, sA, sB);
        }
        gridbar();

        // GCLO (K=192) -> OUT (prelu) + reps
        for (int tile = bid; tile < 128; tile += nb)
            conv_tile(g_XIN2, 128, (size_t)128 * NP, g_H, (size_t)64 * NP,
                      g_Wc2, g_bc2, 192,
                      tile >> 3, (tile & 7) * 64, 1, 0, 0, reps, t, pav, sA, sB);
        gridbar();

        // ewB: imp, x2 -> XG5[0], CG5[0]
        for (int i = gtid; i < BB * NN; i += gstr) {
            int b = i / NN, n = i - b * NN;
            const float* o = g_OUT + (size_t)b * 64 * NP + n;
            const float* h = g_H   + (size_t)b * 64 * NP + n;
            float s = bro[0];
#pragma unroll 8
            for (int c = 0; c < 64; c++)
                s += Wro[c] * o[(size_t)c * NP] + Wro[64 + c] * h[(size_t)c * NP];
            size_t xi = ((size_t)b * NN + n) * TT + t;
            imp[xi] = s;
            int mk = mask[xi];
            float* xg0 = g_XG5 + (size_t)b * XGC * NP + n;
            float x2 = mk ? *xg0 : s;
            *xg0 = x2;
            g_CG5[(size_t)b * XGC * NP + n] = x2;
        }
        gridbar();

        // XFIX(32) + RU_zero(256) in one interval (W x-cols zeroed -> no race)
        for (int tile = bid; tile < 288; tile += nb) {
            if (tile < 32) {
                int n0 = (tile & 7) * 64, z = (tile >> 3) & 1, pw = (tile >> 4) & 1;
                const float* Am = pw ? (z ? g_A2b : g_A2f) : (z ? ab : af);
                diff_tile(g_XG5, g_XG5, Am, pw ? 512 : NN, 1, 0,
                          66 + z * 132 + pw * 66,
                          XGC * NP, XGC * NP, 0, n0, sA, sB);
            } else {
                int idx = tile - 32;
                int gate = idx >> 7, tl = idx & 127;
                conv_tile(g_XG5, 1000, (size_t)XGC * NP, g_XG5, 0,
                          gate ? g_Wu0 : g_Wr0, gate ? bu : br, 330,
                          tl >> 3, (tl & 7) * 64, 0,
                          gate ? g_U : g_R, (size_t)64 * NP,
                          reps, t, pav, sA, sB);
            }
        }
        gridbar();

        // ew_gates: rank-4 x-correction, sigmoids, rh -> CG5; copy x/mf hop rows
        for (int i = gtid; i < BB * 64 * NN; i += gstr) {
            int b = i / (64 * NN), rem = i - b * (64 * NN);
            int o = rem / NN, n = rem - o * NN;
            const float* xgb = g_XG5 + (size_t)b * XGC * NP + n;
            float xh0 = xgb[(size_t)66 * NP],  xh1 = xgb[(size_t)132 * NP];
            float xh2 = xgb[(size_t)198 * NP], xh3 = xgb[(size_t)264 * NP];
            size_t ridx = ((size_t)b * 64 + o) * NP + n;
            float rv = g_R[ridx] + g_Wr4[o*4+0]*xh0 + g_Wr4[o*4+1]*xh1
                                 + g_Wr4[o*4+2]*xh2 + g_Wr4[o*4+3]*xh3;
            float uv = g_U[ridx] + g_Wu4[o*4+0]*xh0 + g_Wu4[o*4+1]*xh1
                                 + g_Wu4[o*4+2]*xh2 + g_Wu4[o*4+3]*xh3;
            float r = 1.f / (1.f + expf(-rv));
            g_U[ridx] = 1.f / (1.f + expf(-uv));
            g_CG5[(size_t)b * XGC * NP + (size_t)(2 + o) * NP + n] = r * g_H[ridx];
        }
        for (int i = gtid; i < BB * 8 * NN; i += gstr) {
            int b = i / (8 * NN), rem = i - b * (8 * NN);
            int s = rem / NN, n = rem - s * NN;
            int slot = 66 * (1 + (s >> 1)) + (s & 1);   // 66,67,132,133,198,199,264,265
            size_t off = (size_t)b * XGC * NP + (size_t)slot * NP + n;
            g_CG5[off] = g_XG5[off];
        }
        gridbar();

        // CGRH: rh hops via A and A^2, both supports (512 tiles)
        for (int tile = bid; tile < 512; tile += nb) {
            int pw = tile >> 8, rem = tile & 255;
            int z = rem >> 7, r2 = rem & 127;
            const float* Am = pw ? (z ? g_A2b : g_A2f) : (z ? ab : af);
            diff_tile(g_CG5, g_CG5, Am, pw ? 512 : NN, 64, 2,
                      68 + z * 132 + pw * 66,
                      XGC * NP, XGC * NP, (r2 >> 3) * 64, (r2 & 7) * 64, sA, sB);
        }
        gridbar();

        // conv c (K=330): tanh + h = u*h + (1-u)*c
        for (int tile = bid; tile < 128; tile += nb)
            conv_tile(g_CG5, 1000, (size_t)XGC * NP, g_CG5, 0, Wc, bc, 330,
                      tile >> 3, (tile & 7) * 64, 4, 0, 0, reps, t, pav, sA, sB);
        gridbar();
    }
}

extern "C" void kernel_launch(void* const* d_in, const int* in_sizes, int n_in,
                              void* d_out, int out_size)
{
    const float* x    = (const float*)d_in[0];
    const float* af   = (const float*)d_in[1];
    const float* ab   = (const float*)d_in[2];
    const int*   mask = (const int*)  d_in[3];
    const float* Wr   = (const float*)d_in[4];
    const float* br   = (const float*)d_in[5];
    const float* Wu   = (const float*)d_in[6];
    const float* bu   = (const float*)d_in[7];
    const float* Wc   = (const float*)d_in[8];
    const float* bc   = (const float*)d_in[9];
    const float* Wfs  = (const float*)d_in[10];
    const float* bfs  = (const float*)d_in[11];
    const float* Wli  = (const float*)d_in[12];
    const float* bli  = (const float*)d_in[13];
    const float* Wgc  = (const float*)d_in[14];
    const float* bgc  = (const float*)d_in[15];
    const float* Wlo  = (const float*)d_in[16];
    const float* blo  = (const float*)d_in[17];
    const float* Wro  = (const float*)d_in[18];
    const float* bro  = (const float*)d_in[19];
    const float* pa   = (const float*)d_in[20];

    float* out_imp  = (float*)d_out;
    float* out_pred = out_imp + (size_t)BB * NN * TT;
    float* out_reps = out_imp + (size_t)2 * BB * NN * TT;

    int dev = 0; cudaGetDevice(&dev);
    int sm = 0;
    cudaDeviceGetAttribute(&sm, cudaDevAttrMultiProcessorCount, dev);
    if (sm <= 0) sm = 148;
    int per = 0;
    cudaOccupancyMaxActiveBlocksPerMultiprocessor(&per, kmain, 256, 0);
    if (per < 1) per = 1;
    if (per > 2) per = 2;
    int nb = sm * per;

    kmain<<<nb, 256>>>(x, af, ab, mask, Wr, br, Wu, bu, Wc, bc,
                       Wfs, bfs, Wli, bli, Wgc, bgc, Wlo, blo, Wro, bro, pa,
                       out_imp, out_pred, out_reps);
}

// round 17
// speedup vs baseline: 1.2062x; 1.0169x over previous
#include <cuda_runtime.h>
#include <math.h>

typedef unsigned long long ull;

#define BB 16
#define NN 500
#define TT 128
#define NP 512
#define XGC 336
#define KT 16

__device__ float g_H   [BB*64 *NP];
__device__ float g_XG5 [BB*XGC*NP];
__device__ float g_CG5 [BB*XGC*NP];
__device__ float g_XIN2[BB*128*NP];
__device__ float g_OUT [BB*64 *NP];
__device__ float g_R   [BB*64 *NP];
__device__ float g_U   [BB*64 *NP];
__device__ float g_A2f [512*512];
__device__ float g_A2b [512*512];
__device__ float g_Wc2 [64*192];
__device__ float g_bc2 [64];
__device__ float g_Wr0 [64*330];
__device__ float g_Wu0 [64*330];
__device__ float g_Wr4 [64*4];
__device__ float g_Wu4 [64*4];

__device__ unsigned g_cnt;
__device__ volatile unsigned g_gen;

__device__ __forceinline__ ull pack2(float x, float y) {
    ull r; asm("mov.b64 %0, {%1,%2};" : "=l"(r) : "f"(x), "f"(y)); return r;
}
__device__ __forceinline__ void unpack2(ull p, float& x, float& y) {
    asm("mov.b64 {%0,%1}, %2;" : "=f"(x), "=f"(y) : "l"(p));
}
__device__ __forceinline__ void fma2(ull& d, ull a, ull b) {
    asm("fma.rn.f32x2 %0, %1, %2, %0;" : "+l"(d) : "l"(a), "l"(b));
}

__device__ __forceinline__ void gridbar() {
    __syncthreads();
    if (threadIdx.x == 0) {
        unsigned gen = g_gen;
        __threadfence();
        if (atomicAdd(&g_cnt, 1u) == gridDim.x - 1u) {
            atomicExch(&g_cnt, 0u);
            __threadfence();
            g_gen = gen + 1u;
        } else {
            while (g_gen == gen) __nanosleep(64);
        }
        __threadfence();
    }
    __syncthreads();
}

// 64x64 tile, 256 threads: tx=tid&15 (4 n), ty=tid>>4 (4 m)
__device__ __forceinline__ void mm16(const float (*sA)[68], const float (*sB)[68],
                                     ull acc[4][2], int tx, int ty) {
#pragma unroll
    for (int kk = 0; kk < KT; kk++) {
        float4 a = *(const float4*)&sA[kk][ty * 4];
        ull b0 = *(const ull*)&sB[kk][tx * 4];
        ull b1 = *(const ull*)&sB[kk][tx * 4 + 2];
        ull ap;
        ap = pack2(a.x, a.x); fma2(acc[0][0], ap, b0); fma2(acc[0][1], ap, b1);
        ap = pack2(a.y, a.y); fma2(acc[1][0], ap, b0); fma2(acc[1][1], ap, b1);
        ap = pack2(a.z, a.z); fma2(acc[2][0], ap, b0); fma2(acc[2][1], ap, b1);
        ap = pack2(a.w, a.w); fma2(acc[3][0], ap, b0); fma2(acc[3][1], ap, b1);
    }
}

// dst[b, dstOff+c, w] = sum_v src[b, srcOff+c, v] * Amat[w, v]; Amat row stride astr
__device__ void diff_tile(const float* __restrict__ src, float* __restrict__ dst,
                          const float* __restrict__ Amat, int astr,
                          int C, int srcOff, int dstOff, int srcBS, int dstBS,
                          int m0, int n0,
                          float (*sAb)[68], float (*sBb)[68])
{
    const int tid = threadIdx.x;
    const int M = C * BB;
    const int r = tid >> 2, kr = tid & 3, koff = kr * 4;

    const float* srow = 0;
    { int gm = m0 + r;
      if (gm < M) { int b = gm / C, c = gm - b * C;
          srow = src + (size_t)b * srcBS + (size_t)(srcOff + c) * NP; } }
    const float* arow = 0;
    { int gn = n0 + r; if (gn < NN) arow = Amat + (size_t)gn * astr; }

    const int tx = tid & 15, ty = tid >> 4;
    ull acc[4][2] = {};
    const float4 Z = make_float4(0.f, 0.f, 0.f, 0.f);
    float4 va = srow ? *(const float4*)(srow + koff) : Z;
    float4 vb = (arow && koff < NN) ? *(const float4*)(arow + koff) : Z;

    int kt = 0;
    for (int k0 = 0; k0 < NN; k0 += KT, kt++) {
        float (*sA)[68] = sAb + (kt & 1) * KT;
        float (*sB)[68] = sBb + (kt & 1) * KT;
        sA[kr*4+0][r] = va.x; sA[kr*4+1][r] = va.y;
        sA[kr*4+2][r] = va.z; sA[kr*4+3][r] = va.w;
        sB[kr*4+0][r] = vb.x; sB[kr*4+1][r] = vb.y;
        sB[kr*4+2][r] = vb.z; sB[kr*4+3][r] = vb.w;
        __syncthreads();
        int kn = k0 + KT;
        if (kn < NN) {
            va = srow ? *(const float4*)(srow + kn + koff) : Z;
            vb = (arow && kn + koff < NN) ? *(const float4*)(arow + kn + koff) : Z;
        }
        mm16(sA, sB, acc, tx, ty);
    }

#pragma unroll
    for (int i = 0; i < 4; i++) {
        int gm = m0 + ty * 4 + i;
        if (gm >= M) continue;
        int b = gm / C, c = gm - b * C;
        float* drow = dst + (size_t)b * dstBS + (size_t)(dstOff + c) * NP;
#pragma unroll
        for (int j = 0; j < 2; j++) {
            int gn = n0 + tx * 4 + 2 * j;
            if (gn < NN) {
                float v0, v1; unpack2(acc[i][j], v0, v1);
                *(float2*)(drow + gn) = make_float2(v0, v1);
            }
        }
    }
}

// A2[w,u] = sum_v A[w,v] * A[v,u]; dst row stride 512
__device__ void a2_tile(const float* __restrict__ A, float* __restrict__ dst,
                        int m0, int n0, float (*sAb)[68], float (*sBb)[68])
{
    const int tid = threadIdx.x;
    const int r = tid >> 2, kr = tid & 3, koff = kr * 4;
    const int kx = tid >> 4, nc = (tid & 15) * 4;
    const int tx = tid & 15, ty = tid >> 4;

    const float* srow = (m0 + r < NN) ? A + (size_t)(m0 + r) * NN : 0;
    const bool ncok = (n0 + nc < NN);

    ull acc[4][2] = {};
    const float4 Z = make_float4(0.f, 0.f, 0.f, 0.f);
    float4 va = srow ? *(const float4*)(srow + koff) : Z;
    float4 vx = (kx < NN && ncok) ? *(const float4*)(A + (size_t)kx * NN + n0 + nc) : Z;

    int kt = 0;
    for (int k0 = 0; k0 < NN; k0 += KT, kt++) {
        float (*sA)[68] = sAb + (kt & 1) * KT;
        float (*sB)[68] = sBb + (kt & 1) * KT;
        sA[kr*4+0][r] = va.x; sA[kr*4+1][r] = va.y;
        sA[kr*4+2][r] = va.z; sA[kr*4+3][r] = va.w;
        *(float4*)&sB[kx][nc] = vx;
        __syncthreads();
        int kn = k0 + KT;
        if (kn < NN) {
            va = (srow && kn + koff < NN) ? *(const float4*)(srow + kn + koff) : Z;
            int kg = kn + kx;
            vx = (kg < NN && ncok) ? *(const float4*)(A + (size_t)kg * NN + n0 + nc) : Z;
        }
        mm16(sA, sB, acc, tx, ty);
    }

#pragma unroll
    for (int i = 0; i < 4; i++) {
        int gm = m0 + ty * 4 + i;
        if (gm >= NN) continue;
        float* drow = dst + (size_t)gm * 512;
#pragma unroll
        for (int j = 0; j < 2; j++) {
            int gn = n0 + tx * 4 + 2 * j;
            if (gn < NN) {
                float v0, v1; unpack2(acc[i][j], v0, v1);
                *(float2*)(drow + gn) = make_float2(v0, v1);
            }
        }
    }
}

// out[b,o,n] = act(sum_k W[o,k]*X[b,k,n] + bias[o]); X = concat(S1,S2)
// mode 0: -> dst (batch stride dstBS) | 1: prelu->g_OUT+reps
// 4: tanh, h=u*h+(1-u)*c
__device__ void conv_tile(const float* __restrict__ S1, int C1, size_t s1BS,
                          const float* __restrict__ S2, size_t s2BS,
                          const float* __restrict__ W, const float* __restrict__ bias,
                          int K, int b, int n0, int mode,
                          float* __restrict__ dst, size_t dstBS,
                          float* __restrict__ reps,
                          int t, float pav,
                          float (*sAb)[68], float (*sBb)[68])
{
    const int tid = threadIdx.x;
    const int o_l = tid & 63, kq = (tid >> 6) * 4;
    const int kx = tid >> 4, nc = (tid & 15) * 4;
    const int tx = tid & 15, ty = tid >> 4;

    ull acc[4][2] = {};
    float w0, w1, w2, w3;
    float4 vx;
    {
        w0 = (kq + 0 < K) ? W[(size_t)o_l * K + kq + 0] : 0.f;
        w1 = (kq + 1 < K) ? W[(size_t)o_l * K + kq + 1] : 0.f;
        w2 = (kq + 2 < K) ? W[(size_t)o_l * K + kq + 2] : 0.f;
        w3 = (kq + 3 < K) ? W[(size_t)o_l * K + kq + 3] : 0.f;
        const float* row = (kx < C1) ? S1 + (size_t)b * s1BS + (size_t)kx * NP
                                     : S2 + (size_t)b * s2BS + (size_t)(kx - C1) * NP;
        vx = *(const float4*)(row + n0 + nc);
    }

    int kt = 0;
    for (int k0 = 0; k0 < K; k0 += KT, kt++) {
        float (*sA)[68] = sAb + (kt & 1) * KT;
        float (*sB)[68] = sBb + (kt & 1) * KT;
        sA[kq+0][o_l] = w0; sA[kq+1][o_l] = w1;
        sA[kq+2][o_l] = w2; sA[kq+3][o_l] = w3;
        *(float4*)&sB[kx][nc] = vx;
        __syncthreads();
        int kn = k0 + KT;
        if (kn < K) {
            int kg0 = kn + kq;
            w0 = (kg0 + 0 < K) ? W[(size_t)o_l * K + kg0 + 0] : 0.f;
            w1 = (kg0 + 1 < K) ? W[(size_t)o_l * K + kg0 + 1] : 0.f;
            w2 = (kg0 + 2 < K) ? W[(size_t)o_l * K + kg0 + 2] : 0.f;
            w3 = (kg0 + 3 < K) ? W[(size_t)o_l * K + kg0 + 3] : 0.f;
            int kg = kn + kx;
            const float* row = (kg < C1) ? S1 + (size_t)b * s1BS + (size_t)kg * NP
                                         : S2 + (size_t)b * s2BS + (size_t)(kg - C1) * NP;
            vx = *(const float4*)(row + n0 + nc);
        }
        mm16(sA, sB, acc, tx, ty);
    }

#pragma unroll
    for (int i = 0; i < 4; i++) {
        int o = ty * 4 + i;
        float bs = bias[o];
        size_t rowIdx = ((size_t)b * 64 + o) * NP;
#pragma unroll
        for (int j = 0; j < 2; j++) {
            int gn = n0 + tx * 4 + 2 * j;
            if (gn >= NN) continue;
            float v0, v1; unpack2(acc[i][j], v0, v1);
            v0 += bs; v1 += bs;
            if (mode == 0) {
                *(float2*)(dst + (size_t)b * dstBS + (size_t)o * NP + gn) =
                    make_float2(v0, v1);
            } else if (mode == 1) {
                float o0 = v0 >= 0.f ? v0 : pav * v0;
                float o1 = v1 >= 0.f ? v1 : pav * v1;
                *(float2*)(g_OUT + rowIdx + gn) = make_float2(o0, o1);
                size_t rb = (((size_t)b * 128 + o) * NN + gn) * TT + t;
                reps[rb] = o0; reps[rb + TT] = o1;
            } else {
                float c0 = tanhf(v0), c1 = tanhf(v1);
                float2 u2 = *(const float2*)(g_U + rowIdx + gn);
                float2 h2 = *(const float2*)(g_H + rowIdx + gn);
                *(float2*)(g_H + rowIdx + gn) =
                    make_float2(u2.x * h2.x + (1.f - u2.x) * c0,
                                u2.y * h2.y + (1.f - u2.y) * c1);
            }
        }
    }
}

__global__ void __launch_bounds__(256, 2) kmain(
    const float* __restrict__ x, const float* __restrict__ af,
    const float* __restrict__ ab, const int* __restrict__ mask,
    const float* __restrict__ Wr,  const float* __restrict__ br,
    const float* __restrict__ Wu,  const float* __restrict__ bu,
    const float* __restrict__ Wc,  const float* __restrict__ bc,
    const float* __restrict__ Wfs, const float* __restrict__ bfs,
    const float* __restrict__ Wli, const float* __restrict__ bli,
    const float* __restrict__ Wgc, const float* __restrict__ bgc,
    const float* __restrict__ Wlo, const float* __restrict__ blo,
    const float* __restrict__ Wro, const float* __restrict__ bro,
    const float* __restrict__ pa,
    float* __restrict__ imp, float* __restrict__ pred, float* __restrict__ reps)
{
    __shared__ __align__(16) float sA[2 * KT][68];
    __shared__ __align__(16) float sB[2 * KT][68];

    const int tid  = threadIdx.x;
    const int nb   = gridDim.x;
    const int bid  = blockIdx.x;
    const int gtid = bid * 256 + tid;
    const int gstr = nb * 256;
    const float pav = *pa;

    // ---- prologue ----
    for (int i = gtid; i < BB * 64 * NP; i += gstr) g_H[i] = 0.f;
    for (int i = gtid; i < 64 * 192; i += gstr) {
        int o = i / 192, k = i - o * 192;
        float s;
        if (k < 128) {
            s = 0.f;
            for (int j = 0; j < 64; j++) s += Wlo[o * 128 + j] * Wgc[j * 128 + k];
        } else s = Wlo[o * 128 + 64 + (k - 128)];
        g_Wc2[i] = s;
    }
    for (int i = gtid; i < 64; i += gstr) {
        float s = blo[i];
        for (int j = 0; j < 64; j++) s += Wlo[i * 128 + j] * bgc[j];
        g_bc2[i] = s;
    }
    // zero-x-column gate weights + rank-4 columns (slots 66,132,198,264)
    for (int i = gtid; i < 64 * 330; i += gstr) {
        int k = i % 330;
        bool xs = (k == 66 || k == 132 || k == 198 || k == 264);
        g_Wr0[i] = xs ? 0.f : Wr[i];
        g_Wu0[i] = xs ? 0.f : Wu[i];
    }
    for (int i = gtid; i < 64 * 4; i += gstr) {
        int o = i >> 2, j = i & 3;
        g_Wr4[i] = Wr[o * 330 + 66 * (j + 1)];
        g_Wu4[i] = Wu[o * 330 + 66 * (j + 1)];
    }
    for (int tile = bid; tile < 128; tile += nb) {
        int z = tile >> 6, rem = tile & 63;
        a2_tile(z ? ab : af, z ? g_A2b : g_A2f,
                (rem >> 3) * 64, (rem & 7) * 64, sA, sB);
    }
    gridbar();

    for (int t = 0; t < TT; t++) {
        // ewA: pred, x1, mf; pack XG5 h; CG5 mf; reps h-half
        for (int i = gtid; i < BB * NN; i += gstr) {
            int b = i / NN, n = i - b * NN;
            const float* h = g_H + (size_t)b * 64 * NP + n;
            float* xg = g_XG5 + (size_t)b * XGC * NP + n;
            float* rb = reps + (((size_t)b * 128 + 64) * NN + n) * TT + t;
            float s = bfs[0];
#pragma unroll 8
            for (int c = 0; c < 64; c++) {
                float hv = h[(size_t)c * NP];
                s += Wfs[c] * hv;
                xg[(size_t)(2 + c) * NP] = hv;
                rb[(size_t)c * NN * TT] = hv;
            }
            size_t xi = ((size_t)b * NN + n) * TT + t;
            pred[xi] = s;
            int mk = mask[xi];
            xg[0]  = mk ? x[xi] : s;
            xg[NP] = (float)mk;
            g_CG5[(size_t)b * XGC * NP + NP + n] = (float)mk;
        }
        gridbar();

        // DIFF544: XG hops of [x1, mf, h] via A and A^2, both supports
        for (int tile = bid; tile < 544; tile += nb) {
            int hop = tile / 272, rem = tile - hop * 272;
            int z = rem / 136, r2 = rem - z * 136;
            const float* Am = hop ? (z ? g_A2b : g_A2f) : (z ? ab : af);
            diff_tile(g_XG5, g_XG5, Am, hop ? 512 : NN, 66, 0,
                      66 + z * 132 + hop * 66,
                      XGC * NP, XGC * NP, (r2 >> 3) * 64, (r2 & 7) * 64, sA, sB);
        }
        gridbar();

        // LI2: XIN2[z*64..] = W_li . hop1_z block (K=66) — replaces li+diff1
        for (int tile = bid; tile < 256; tile += nb) {
            int z = tile >> 7, tl = tile & 127;
            conv_tile(g_XG5 + (size_t)(66 + z * 132) * NP, 1000, (size_t)XGC * NP,
                      g_XG5, 0, Wli, bli, 66,
                      tl >> 3, (tl & 7) * 64, 0,
                      g_XIN2 + (size_t)z * 64 * NP, (size_t)128 * NP,
                      reps, t, pav, sA, sB);
        }
        gridbar();

        // GCLO (K=192) -> OUT (prelu) + reps
        for (int tile = bid; tile < 128; tile += nb)
            conv_tile(g_XIN2, 128, (size_t)128 * NP, g_H, (size_t)64 * NP,
                      g_Wc2, g_bc2, 192,
                      tile >> 3, (tile & 7) * 64, 1, 0, 0, reps, t, pav, sA, sB);
        gridbar();

        // ewB: imp, x2 -> XG5[0], CG5[0]
        for (int i = gtid; i < BB * NN; i += gstr) {
            int b = i / NN, n = i - b * NN;
            const float* o = g_OUT + (size_t)b * 64 * NP + n;
            const float* h = g_H   + (size_t)b * 64 * NP + n;
            float s = bro[0];
#pragma unroll 8
            for (int c = 0; c < 64; c++)
                s += Wro[c] * o[(size_t)c * NP] + Wro[64 + c] * h[(size_t)c * NP];
            size_t xi = ((size_t)b * NN + n) * TT + t;
            imp[xi] = s;
            int mk = mask[xi];
            float* xg0 = g_XG5 + (size_t)b * XGC * NP + n;
            float x2 = mk ? *xg0 : s;
            *xg0 = x2;
            g_CG5[(size_t)b * XGC * NP + n] = x2;
        }
        gridbar();

        // XFIX(32) + RU_zero(256) in one interval (W x-cols zeroed -> no race)
        for (int tile = bid; tile < 288; tile += nb) {
            if (tile < 32) {
                int n0 = (tile & 7) * 64, z = (tile >> 3) & 1, pw = (tile >> 4) & 1;
                const float* Am = pw ? (z ? g_A2b : g_A2f) : (z ? ab : af);
                diff_tile(g_XG5, g_XG5, Am, pw ? 512 : NN, 1, 0,
                          66 + z * 132 + pw * 66,
                          XGC * NP, XGC * NP, 0, n0, sA, sB);
            } else {
                int idx = tile - 32;
                int gate = idx >> 7, tl = idx & 127;
                conv_tile(g_XG5, 1000, (size_t)XGC * NP, g_XG5, 0,
                          gate ? g_Wu0 : g_Wr0, gate ? bu : br, 330,
                          tl >> 3, (tl & 7) * 64, 0,
                          gate ? g_U : g_R, (size_t)64 * NP,
                          reps, t, pav, sA, sB);
            }
        }
        gridbar();

        // ew_gates: rank-4 x-correction, sigmoids, rh -> CG5; copy x/mf hop rows
        for (int i = gtid; i < BB * 64 * NN; i += gstr) {
            int b = i / (64 * NN), rem = i - b * (64 * NN);
            int o = rem / NN, n = rem - o * NN;
            const float* xgb = g_XG5 + (size_t)b * XGC * NP + n;
            float xh0 = xgb[(size_t)66 * NP],  xh1 = xgb[(size_t)132 * NP];
            float xh2 = xgb[(size_t)198 * NP], xh3 = xgb[(size_t)264 * NP];
            size_t ridx = ((size_t)b * 64 + o) * NP + n;
            float rv = g_R[ridx] + g_Wr4[o*4+0]*xh0 + g_Wr4[o*4+1]*xh1
                                 + g_Wr4[o*4+2]*xh2 + g_Wr4[o*4+3]*xh3;
            float uv = g_U[ridx] + g_Wu4[o*4+0]*xh0 + g_Wu4[o*4+1]*xh1
                                 + g_Wu4[o*4+2]*xh2 + g_Wu4[o*4+3]*xh3;
            float r = 1.f / (1.f + expf(-rv));
            g_U[ridx] = 1.f / (1.f + expf(-uv));
            g_CG5[(size_t)b * XGC * NP + (size_t)(2 + o) * NP + n] = r * g_H[ridx];
        }
        for (int i = gtid; i < BB * 8 * NN; i += gstr) {
            int b = i / (8 * NN), rem = i - b * (8 * NN);
            int s = rem / NN, n = rem - s * NN;
            int slot = 66 * (1 + (s >> 1)) + (s & 1);   // 66,67,132,133,198,199,264,265
            size_t off = (size_t)b * XGC * NP + (size_t)slot * NP + n;
            g_CG5[off] = g_XG5[off];
        }
        gridbar();

        // CGRH: rh hops via A and A^2, both supports (512 tiles)
        for (int tile = bid; tile < 512; tile += nb) {
            int pw = tile >> 8, rem = tile & 255;
            int z = rem >> 7, r2 = rem & 127;
            const float* Am = pw ? (z ? g_A2b : g_A2f) : (z ? ab : af);
            diff_tile(g_CG5, g_CG5, Am, pw ? 512 : NN, 64, 2,
                      68 + z * 132 + pw * 66,
                      XGC * NP, XGC * NP, (r2 >> 3) * 64, (r2 & 7) * 64, sA, sB);
        }
        gridbar();

        // conv c (K=330): tanh + h = u*h + (1-u)*c
        for (int tile = bid; tile < 128; tile += nb)
            conv_tile(g_CG5, 1000, (size_t)XGC * NP, g_CG5, 0, Wc, bc, 330,
                      tile >> 3, (tile & 7) * 64, 4, 0, 0, reps, t, pav, sA, sB);
        gridbar();
    }
}

extern "C" void kernel_launch(void* const* d_in, const int* in_sizes, int n_in,
                              void* d_out, int out_size)
{
    const float* x    = (const float*)d_in[0];
    const float* af   = (const float*)d_in[1];
    const float* ab   = (const float*)d_in[2];
    const int*   mask = (const int*)  d_in[3];
    const float* Wr   = (const float*)d_in[4];
    const float* br   = (const float*)d_in[5];
    const float* Wu   = (const float*)d_in[6];
    const float* bu   = (const float*)d_in[7];
    const float* Wc   = (const float*)d_in[8];
    const float* bc   = (const float*)d_in[9];
    const float* Wfs  = (const float*)d_in[10];
    const float* bfs  = (const float*)d_in[11];
    const float* Wli  = (const float*)d_in[12];
    const float* bli  = (const float*)d_in[13];
    const float* Wgc  = (const float*)d_in[14];
    const float* bgc  = (const float*)d_in[15];
    const float* Wlo  = (const float*)d_in[16];
    const float* blo  = (const float*)d_in[17];
    const float* Wro  = (const float*)d_in[18];
    const float* bro  = (const float*)d_in[19];
    const float* pa   = (const float*)d_in[20];

    float* out_imp  = (float*)d_out;
    float* out_pred = out_imp + (size_t)BB * NN * TT;
    float* out_reps = out_imp + (size_t)2 * BB * NN * TT;

    int dev = 0; cudaGetDevice(&dev);
    int sm = 0;
    cudaDeviceGetAttribute(&sm, cudaDevAttrMultiProcessorCount, dev);
    if (sm <= 0) sm = 148;
    int per = 0;
    cudaOccupancyMaxActiveBlocksPerMultiprocessor(&per, kmain, 256, 0);
    if (per < 1) per = 1;
    if (per > 2) per = 2;
    int nb = sm * per;

    kmain<<<nb, 256>>>(x, af, ab, mask, Wr, br, Wu, bu, Wc, bc,
                       Wfs, bfs, Wli, bli, Wgc, bgc, Wlo, blo, Wro, bro, pa,
                       out_imp, out_pred, out_reps);
}